// round 2
// baseline (speedup 1.0000x reference)
#include <cuda_runtime.h>
#include <math.h>

// Problem constants (fixed shapes from reference)
#define B_    32
#define INC_  10
#define LIN_  16384
#define CH_   20
#define NPOLY 12
#define MM_   6
#define NB_   4
// lengths: l0=16434, each block shrinks by 12 -> 16422,16410,16398,16386

#define BUFN 10520000  // >= 32*20*16434 = 10,517,760 ; also >= 32*120*2738

__device__ float g_xa[BUFN];
__device__ float g_xb[BUFN];
__device__ float g_y1[BUFN];
__device__ float g_y2[BUFN];
__device__ float g_Lg[BUFN];

__device__ __forceinline__ float gelu_f(float x) {
    return 0.5f * x * (1.0f + erff(x * 0.7071067811865476f));
}

// ---------------------------------------------------------------------------
// First conv: input (B,10,16384) wrap-padded (25, 27) then conv3 -> (B,20,16434)
// ---------------------------------------------------------------------------
__global__ void __launch_bounds__(128) k_first(
    const float* __restrict__ in, const float* __restrict__ w,
    float* __restrict__ out, int lout)
{
    __shared__ float sw[CH_ * INC_ * 3];  // 600
    int tid = threadIdx.x;
    for (int i = tid; i < CH_ * INC_ * 3; i += blockDim.x) sw[i] = w[i];
    __syncthreads();

    int b = blockIdx.y;
    int t = blockIdx.x * blockDim.x + tid;
    if (t >= lout) return;

    int base = t - 25;
    int i0 = base;     if (i0 < 0) i0 += LIN_; else if (i0 >= LIN_) i0 -= LIN_;
    int i1 = base + 1; if (i1 < 0) i1 += LIN_; else if (i1 >= LIN_) i1 -= LIN_;
    int i2 = base + 2; if (i2 < 0) i2 += LIN_; else if (i2 >= LIN_) i2 -= LIN_;

    const float* inb = in + (size_t)b * INC_ * LIN_;
    float acc[CH_];
#pragma unroll
    for (int co = 0; co < CH_; co++) acc[co] = 0.f;

#pragma unroll
    for (int ci = 0; ci < INC_; ci++) {
        float v0 = inb[ci * LIN_ + i0];
        float v1 = inb[ci * LIN_ + i1];
        float v2 = inb[ci * LIN_ + i2];
#pragma unroll
        for (int co = 0; co < CH_; co++) {
            const float* wp = sw + (co * INC_ + ci) * 3;
            acc[co] = fmaf(wp[0], v0, fmaf(wp[1], v1, fmaf(wp[2], v2, acc[co])));
        }
    }
    float* ob = out + (size_t)b * CH_ * lout;
#pragma unroll
    for (int co = 0; co < CH_; co++) ob[co * lout + t] = acc[co];
}

// ---------------------------------------------------------------------------
// conv3 20->20, VALID. 2 positions per thread. Optional exact-gelu on output.
// ---------------------------------------------------------------------------
template <bool DO_GELU>
__global__ void __launch_bounds__(128) k_conv20(
    const float* __restrict__ x, const float* __restrict__ w,
    float* __restrict__ out, int lin)
{
    __shared__ float sw[CH_ * CH_ * 3];  // 1200
    int tid = threadIdx.x;
    for (int i = tid; i < CH_ * CH_ * 3; i += blockDim.x) sw[i] = w[i];
    __syncthreads();

    int lout = lin - 2;
    int b = blockIdx.y;
    int t0 = (blockIdx.x * blockDim.x + tid) * 2;
    if (t0 >= lout) return;
    bool has2 = (t0 + 1 < lout);

    const float* xb = x + (size_t)b * CH_ * lin;
    float a0[CH_], a1[CH_];
#pragma unroll
    for (int co = 0; co < CH_; co++) { a0[co] = 0.f; a1[co] = 0.f; }

#pragma unroll
    for (int ci = 0; ci < CH_; ci++) {
        const float* xp = xb + ci * lin + t0;
        float v0 = xp[0], v1 = xp[1], v2 = xp[2];
        float v3 = has2 ? xp[3] : 0.f;
#pragma unroll
        for (int co = 0; co < CH_; co++) {
            const float* wp = sw + (co * CH_ + ci) * 3;
            float w0 = wp[0], w1 = wp[1], w2 = wp[2];
            a0[co] = fmaf(w0, v0, fmaf(w1, v1, fmaf(w2, v2, a0[co])));
            a1[co] = fmaf(w0, v1, fmaf(w1, v2, fmaf(w2, v3, a1[co])));
        }
    }
    float* ob = out + (size_t)b * CH_ * lout;
#pragma unroll
    for (int co = 0; co < CH_; co++) {
        float u0 = a0[co], u1 = a1[co];
        if (DO_GELU) { u0 = gelu_f(u0); u1 = gelu_f(u1); }
        ob[co * lout + t0] = u0;
        if (has2) ob[co * lout + t0 + 1] = u1;
    }
}

// ---------------------------------------------------------------------------
// Legendre decomposition + cross-channel block-diag mixing.
// Flat mode-major axis: q = mi*20 + ci, q in [0,120).
//   v[q,t] = sum_k (fd[mi,k]*0.5) * x[b, ci, 6t+k]
//   u[p,t] = sum_i lm[p/6, p%6, i] * v[6*(p/6)+i, t]
// Output layout: Lg[((b*6 + mo)*20 + co)*ll + t] with p = mo*20 + co.
// Block: (32 t-positions) x (20 groups); one b per blockIdx.y.
// ---------------------------------------------------------------------------
#define TB_ 32
__global__ void __launch_bounds__(640) k_legmix(
    const float* __restrict__ x, const float* __restrict__ lm_g,
    const float* __restrict__ fd, float* __restrict__ Lg, int lin, int ll)
{
    __shared__ float xs[CH_][TB_ * 6 + 6];   // 20 x 198
    __shared__ float fd2[MM_ * NPOLY];       // 72
    __shared__ float lm[CH_ * MM_ * MM_];    // 720

    int b = blockIdx.y;
    int T0 = blockIdx.x * TB_;
    int tid = threadIdx.y * TB_ + threadIdx.x;  // 0..639

    for (int i = tid; i < MM_ * NPOLY; i += 640) fd2[i] = 0.5f * fd[i];
    for (int i = tid; i < CH_ * MM_ * MM_; i += 640) lm[i] = lm_g[i];
    // load x tile: positions [6*T0, 6*T0 + 198) per channel
    for (int i = tid; i < CH_ * (TB_ * 6 + 6); i += 640) {
        int ci = i / (TB_ * 6 + 6);
        int j  = i % (TB_ * 6 + 6);
        int pos = 6 * T0 + j;
        xs[ci][j] = (pos < lin) ? x[((size_t)b * CH_ + ci) * lin + pos] : 0.f;
    }
    __syncthreads();

    int tloc = threadIdx.x;
    int g = threadIdx.y;
    int t = T0 + tloc;
    if (t >= ll) return;

    // v[i] for flat q = 6g+i
    float v[MM_];
#pragma unroll
    for (int i = 0; i < MM_; i++) {
        int q  = 6 * g + i;
        int mi = q / CH_;
        int ci = q % CH_;
        float s = 0.f;
#pragma unroll
        for (int k = 0; k < NPOLY; k++)
            s = fmaf(fd2[mi * NPOLY + k], xs[ci][6 * tloc + k], s);
        v[i] = s;
    }
    // u[o] = sum_i lm[g,o,i] * v[i]; write at p = 6g+o -> (mo, co)
#pragma unroll
    for (int o = 0; o < MM_; o++) {
        float s = 0.f;
#pragma unroll
        for (int i = 0; i < MM_; i++)
            s = fmaf(lm[(g * MM_ + o) * MM_ + i], v[i], s);
        int p  = 6 * g + o;
        int mo = p / CH_;
        int co = p % CH_;
        Lg[(((size_t)b * MM_ + mo) * CH_ + co) * ll + t] = s;
    }
}

// ---------------------------------------------------------------------------
// Overlap-add reconstruction + residual add + gelu.
// Lg layout [b][mo][co][ll]; for output t: p=t+6, t0=p/6, k0=p%6:
//   rec = sum_mo Lg[mo,t0]*fr[mo,k0] + Lg[mo,t0-1]*fr[mo,k0+6]
//   out = gelu(rec + y2[t+4]), y2 row length = lout+8
// ---------------------------------------------------------------------------
__global__ void __launch_bounds__(128) k_recon(
    const float* __restrict__ Lg, const float* __restrict__ fr,
    const float* __restrict__ y2, float* __restrict__ out, int ll, int lout)
{
    __shared__ float sfr[MM_ * NPOLY];
    int tid = threadIdx.x;
    if (tid < MM_ * NPOLY) sfr[tid] = fr[tid];
    __syncthreads();

    int bc = blockIdx.y;
    int b = bc / CH_, co = bc % CH_;
    int t = blockIdx.x * blockDim.x + tid;
    if (t >= lout) return;

    int p = t + 6;
    int t0 = p / 6;
    int k0 = p - 6 * t0;

    const float* Lo = Lg + (((size_t)b * MM_) * CH_ + co) * ll;
    size_t mstride = (size_t)CH_ * ll;
    float s = 0.f;
#pragma unroll
    for (int m = 0; m < MM_; m++) {
        s = fmaf(Lo[m * mstride + t0],     sfr[m * NPOLY + k0],     s);
        s = fmaf(Lo[m * mstride + t0 - 1], sfr[m * NPOLY + k0 + 6], s);
    }
    int liny2 = lout + 8;
    float val = s + y2[(size_t)bc * liny2 + t + 4];
    out[(size_t)bc * lout + t] = gelu_f(val);
}

// ---------------------------------------------------------------------------
// Final: out[b,t] = sum_o w_out[o] * gelu(sum_c w11[o,c] * x[b,c,t]), t<16384
// ---------------------------------------------------------------------------
__global__ void __launch_bounds__(128) k_final(
    const float* __restrict__ x, const float* __restrict__ w11,
    const float* __restrict__ w_out, float* __restrict__ out, int lin)
{
    __shared__ float sw[128 * CH_];  // 2560
    __shared__ float so[128];
    int tid = threadIdx.x;
    for (int i = tid; i < 128 * CH_; i += blockDim.x) sw[i] = w11[i];
    if (tid < 128) so[tid] = w_out[tid];
    __syncthreads();

    int b = blockIdx.y;
    int t = blockIdx.x * blockDim.x + tid;
    if (t >= LIN_) return;

    const float* xb = x + (size_t)b * CH_ * lin + t;
    float xv[CH_];
#pragma unroll
    for (int c = 0; c < CH_; c++) xv[c] = xb[c * lin];

    float acc = 0.f;
#pragma unroll 4
    for (int o = 0; o < 128; o++) {
        float h = 0.f;
#pragma unroll
        for (int c = 0; c < CH_; c++) h = fmaf(sw[o * CH_ + c], xv[c], h);
        acc = fmaf(so[o], gelu_f(h), acc);
    }
    out[(size_t)b * LIN_ + t] = acc;
}

// ---------------------------------------------------------------------------
extern "C" void kernel_launch(void* const* d_in, const int* in_sizes, int n_in,
                              void* d_out, int out_size)
{
    const float* input  = (const float*)d_in[0];
    const float* w_first= (const float*)d_in[1];
    const float* conv_a = (const float*)d_in[2];
    const float* conv_b = (const float*)d_in[3];
    const float* lin_m  = (const float*)d_in[4];
    const float* w11    = (const float*)d_in[5];
    const float* w_out  = (const float*)d_in[6];
    const float* filt_d = (const float*)d_in[7];
    const float* filt_r = (const float*)d_in[8];
    float* out = (float*)d_out;

    float *xa, *xb, *y1, *y2, *Lg;
    cudaGetSymbolAddress((void**)&xa, g_xa);
    cudaGetSymbolAddress((void**)&xb, g_xb);
    cudaGetSymbolAddress((void**)&y1, g_y1);
    cudaGetSymbolAddress((void**)&y2, g_y2);
    cudaGetSymbolAddress((void**)&Lg, g_Lg);

    int l = 16434;  // 16384 + 25 + 27 - 2
    {
        dim3 g((l + 127) / 128, B_);
        k_first<<<g, 128>>>(input, w_first, xa, l);
    }

    float* cur = xa;
    float* alt = xb;
    for (int i = 0; i < NB_; i++) {
        int l1 = l - 2;        // after conv_a
        int l2 = l - 4;        // after conv_b
        int ll = l / 6 - 1;    // decomposition length
        int lo = l - 12;       // block output length

        dim3 ga((l1 + 255) / 256, B_);
        k_conv20<true><<<ga, 128>>>(cur, conv_a + i * CH_ * CH_ * 3, y1, l);

        dim3 gb((l2 + 255) / 256, B_);
        k_conv20<false><<<gb, 128>>>(y1, conv_b + i * CH_ * CH_ * 3, y2, l1);

        dim3 gl((ll + TB_ - 1) / TB_, B_);
        k_legmix<<<gl, dim3(TB_, CH_)>>>(cur, lin_m + i * CH_ * MM_ * MM_,
                                         filt_d, Lg, l, ll);

        dim3 gr((lo + 127) / 128, B_ * CH_);
        k_recon<<<gr, 128>>>(Lg, filt_r, y2, alt, ll, lo);

        float* tmp = cur; cur = alt; alt = tmp;
        l = lo;
    }

    dim3 gf((LIN_ + 127) / 128, B_);
    k_final<<<gf, 128>>>(cur, w11, w_out, out, l);
}